// round 7
// baseline (speedup 1.0000x reference)
#include <cuda_runtime.h>
#include <cuda_fp16.h>
#include <cuda_bf16.h>

#define N_NODES 100000
#define N_EDGES 1600000
#define IN_F    128
#define HEADS   8
#define OUT_F   16
#define HD      128   // HEADS*OUT_F
#define NEG_SLOPE 0.2f

// ---------------- scratch (device globals; no allocation allowed) ------------
__device__ __align__(16) float  g_h  [N_NODES * HD];   // fp32 projected features
__device__ __align__(16) __half g_hh [N_NODES * HD];   // fp16 copy for edge gathers
__device__ __align__(16) float  g_el [N_NODES * HEADS];
__device__ __align__(16) float  g_er [N_NODES * HEADS];
__device__ __align__(16) int    g_deg   [N_NODES];
__device__ __align__(16) int    g_off   [N_NODES + 4];
__device__ __align__(16) int    g_cursor[N_NODES];
__device__ __align__(16) int    g_csr_src[N_EDGES];
__device__ int g_bsum[32];
__device__ int g_boff[32];

// ---------------- K1: h = feats @ W, el/er  (8 rows per warp) ----------------
#define K1_BLOCK 256
#define K1_WARPS (K1_BLOCK / 32)                              // 8
#define K1_ROWS  8
#define K1_SMEM  (128*128*4 + K1_WARPS*K1_ROWS*128*4 + 2*128*4)  // 99328 B

__global__ void __launch_bounds__(K1_BLOCK, 2)
k_proj(const float* __restrict__ feats, const float* __restrict__ W,
       const float* __restrict__ attn_l, const float* __restrict__ attn_r)
{
    extern __shared__ float smem[];
    float* Ws   = smem;                              // 128*128
    float* frow = Ws + 128 * 128;                    // 8 warps * 8 rows * 128
    float* al   = frow + K1_WARPS * K1_ROWS * 128;   // 128
    float* ar   = al + 128;                          // 128

    const int tid = threadIdx.x;

    for (int i = tid; i < 128 * 128 / 4; i += K1_BLOCK)
        ((float4*)Ws)[i] = ((const float4*)W)[i];
    if (tid < 128) { al[tid] = attn_l[tid]; ar[tid] = attn_r[tid]; }
    __syncthreads();

    const int warp = tid >> 5, lane = tid & 31;
    const int gw = blockIdx.x * K1_WARPS + warp;
    const int nw = gridDim.x * K1_WARPS;
    float* fr = frow + warp * K1_ROWS * 128;
    const int head  = lane >> 2;
    const int cbase = lane * 4;
    const float4* Ws4 = (const float4*)Ws;

    for (int base = gw * K1_ROWS; base < N_NODES; base += nw * K1_ROWS) {
        #pragma unroll
        for (int r = 0; r < K1_ROWS; r++)
            ((float4*)(fr + r * 128))[lane] = ((const float4*)(feats + (base + r) * IN_F))[lane];
        __syncwarp();

        float4 acc[K1_ROWS];
        #pragma unroll
        for (int r = 0; r < K1_ROWS; r++) acc[r] = make_float4(0.f, 0.f, 0.f, 0.f);

        for (int k4 = 0; k4 < 128; k4 += 4) {
            float f[K1_ROWS][4];
            #pragma unroll
            for (int r = 0; r < K1_ROWS; r++) {
                float4 F = *(const float4*)(fr + r * 128 + k4);
                f[r][0] = F.x; f[r][1] = F.y; f[r][2] = F.z; f[r][3] = F.w;
            }
            #pragma unroll
            for (int kk = 0; kk < 4; kk++) {
                float4 w = Ws4[(k4 + kk) * 32 + lane];
                #pragma unroll
                for (int r = 0; r < K1_ROWS; r++) {
                    acc[r].x += f[r][kk] * w.x;
                    acc[r].y += f[r][kk] * w.y;
                    acc[r].z += f[r][kk] * w.z;
                    acc[r].w += f[r][kk] * w.w;
                }
            }
        }

        #pragma unroll
        for (int r = 0; r < K1_ROWS; r++) {
            float4 a = acc[r];
            int row = base + r;
            float pl = a.x * al[cbase] + a.y * al[cbase+1] + a.z * al[cbase+2] + a.w * al[cbase+3];
            float pr = a.x * ar[cbase] + a.y * ar[cbase+1] + a.z * ar[cbase+2] + a.w * ar[cbase+3];
            pl += __shfl_xor_sync(0xffffffffu, pl, 1);
            pl += __shfl_xor_sync(0xffffffffu, pl, 2);
            pr += __shfl_xor_sync(0xffffffffu, pr, 1);
            pr += __shfl_xor_sync(0xffffffffu, pr, 2);
            if ((lane & 3) == 0) {
                g_el[row * HEADS + head] = pl;
                g_er[row * HEADS + head] = pr;
            }
            ((float4*)(g_h + row * HD))[lane] = a;
            // fp16 copy for the edge-gather kernel
            __half2 p01 = __floats2half2_rn(a.x, a.y);
            __half2 p23 = __floats2half2_rn(a.z, a.w);
            uint2 hu;
            *reinterpret_cast<__half2*>(&hu.x) = p01;
            *reinterpret_cast<__half2*>(&hu.y) = p23;
            ((uint2*)(g_hh + row * HD))[lane] = hu;
        }
        __syncwarp();
    }
}

// ---------------- CSR build ---------------------------------------------------
__global__ void __launch_bounds__(512)
k_zero()
{
    for (int i = blockIdx.x * 512 + threadIdx.x; i < N_NODES; i += gridDim.x * 512)
        g_deg[i] = 0;
}

__global__ void __launch_bounds__(256)
k_hist(const int* __restrict__ dst)
{
    int i = blockIdx.x * 256 + threadIdx.x;          // 4 edges per thread
    if (i * 4 >= N_EDGES) return;
    int4 d4 = ((const int4*)dst)[i];
    atomicAdd(&g_deg[d4.x], 1);
    atomicAdd(&g_deg[d4.y], 1);
    atomicAdd(&g_deg[d4.z], 1);
    atomicAdd(&g_deg[d4.w], 1);
}

// ---- parallel scan: 25 blocks of 4096 elems, then block-sum scan, then add --
#define SCAN_BLOCKS ((N_NODES + 4095) / 4096)   // 25

__global__ void __launch_bounds__(1024)
k_scan1()
{
    __shared__ int wsum[32];
    const int tid = threadIdx.x, lane = tid & 31, warp = tid >> 5;
    const int i0 = blockIdx.x * 4096 + tid * 4;

    int4 v = (i0 < N_NODES) ? ((const int4*)g_deg)[i0 >> 2] : make_int4(0, 0, 0, 0);
    int t = v.x + v.y + v.z + v.w;
    int x = t;
    #pragma unroll
    for (int o = 1; o < 32; o <<= 1) {
        int y = __shfl_up_sync(0xffffffffu, x, o);
        if (lane >= o) x += y;
    }
    if (lane == 31) wsum[warp] = x;
    __syncthreads();
    if (warp == 0) {
        int s = wsum[lane];
        #pragma unroll
        for (int o = 1; o < 32; o <<= 1) {
            int y = __shfl_up_sync(0xffffffffu, s, o);
            if (lane >= o) s += y;
        }
        wsum[lane] = s;
    }
    __syncthreads();
    int warpoff = (warp == 0) ? 0 : wsum[warp - 1];
    int excl = warpoff + x - t;             // block-local exclusive prefix
    if (i0 < N_NODES) {
        int4 o;
        o.x = excl;
        o.y = o.x + v.x;
        o.z = o.y + v.y;
        o.w = o.z + v.z;
        ((int4*)g_off)[i0 >> 2] = o;
    }
    if (tid == 0) g_bsum[blockIdx.x] = wsum[31];
}

__global__ void __launch_bounds__(32)
k_scan2()
{
    int lane = threadIdx.x;
    int v = (lane < SCAN_BLOCKS) ? g_bsum[lane] : 0;
    int x = v;
    #pragma unroll
    for (int o = 1; o < 32; o <<= 1) {
        int y = __shfl_up_sync(0xffffffffu, x, o);
        if (lane >= o) x += y;
    }
    if (lane < SCAN_BLOCKS) g_boff[lane] = x - v;   // exclusive
}

__global__ void __launch_bounds__(1024)
k_scan3()
{
    const int i0 = blockIdx.x * 4096 + threadIdx.x * 4;
    if (i0 < N_NODES) {
        int boff = g_boff[blockIdx.x];
        int4 o = ((const int4*)g_off)[i0 >> 2];
        o.x += boff; o.y += boff; o.z += boff; o.w += boff;
        ((int4*)g_off)[i0 >> 2] = o;
        ((int4*)g_cursor)[i0 >> 2] = o;
    }
    if (blockIdx.x == 0 && threadIdx.x == 0) g_off[N_NODES] = N_EDGES;
}

__global__ void __launch_bounds__(256)
k_scatter(const int* __restrict__ src, const int* __restrict__ dst)
{
    int i = blockIdx.x * 256 + threadIdx.x;          // 4 edges per thread
    if (i * 4 >= N_EDGES) return;
    int4 s4 = ((const int4*)src)[i];
    int4 d4 = ((const int4*)dst)[i];
    int p0 = atomicAdd(&g_cursor[d4.x], 1);
    int p1 = atomicAdd(&g_cursor[d4.y], 1);
    int p2 = atomicAdd(&g_cursor[d4.z], 1);
    int p3 = atomicAdd(&g_cursor[d4.w], 1);
    g_csr_src[p0] = s4.x;
    g_csr_src[p1] = s4.y;
    g_csr_src[p2] = s4.z;
    g_csr_src[p3] = s4.w;
}

// ---------------- K3: warp per dst node, fp16 gather --------------------------
__global__ void __launch_bounds__(256)
k_agg(const float* __restrict__ bias, float* __restrict__ out)
{
    int gw = (blockIdx.x * 256 + threadIdx.x) >> 5;
    int lane = threadIdx.x & 31;
    if (gw >= N_NODES) return;
    const int d = gw;
    const int head = lane >> 2;

    int start = g_off[d], end = g_off[d + 1];
    float erd = (lane < 8) ? g_er[d * HEADS + lane] : 0.f;
    float sum = 0.f;
    float4 acc = {0.f, 0.f, 0.f, 0.f};

    for (int base = start; base < end; base += 32) {
        int idx = base + lane;
        int myS = (idx < end) ? g_csr_src[idx] : 0;
        int cnt = min(32, end - base);
        #pragma unroll 4
        for (int t = 0; t < cnt; t++) {
            int s = __shfl_sync(0xffffffffu, myS, t);
            float ex = 0.f;
            if (lane < 8) {
                float a = g_el[s * HEADS + lane] + erd;
                a = a > 0.f ? a : NEG_SLOPE * a;
                ex = __expf(a);
                sum += ex;
            }
            float exh = __shfl_sync(0xffffffffu, ex, head);
            uint2 hv = ((const uint2*)(g_hh + s * HD))[lane];   // 8B/lane = 256B/edge
            __half2 h01 = *reinterpret_cast<__half2*>(&hv.x);
            __half2 h23 = *reinterpret_cast<__half2*>(&hv.y);
            float2 f01 = __half22float2(h01);
            float2 f23 = __half22float2(h23);
            acc.x += exh * f01.x; acc.y += exh * f01.y;
            acc.z += exh * f23.x; acc.w += exh * f23.y;
        }
    }

    float sumh = __shfl_sync(0xffffffffu, sum, head);
    float inv = (end > start) ? 1.f / sumh : 0.f;   // zero in-degree guard
    float4 hd = ((const float4*)(g_h + d * HD))[lane];   // fp32 residual
    float4 b  = ((const float4*)bias)[lane];
    float4 o;
    o.x = acc.x * inv + hd.x + b.x;
    o.y = acc.y * inv + hd.y + b.y;
    o.z = acc.z * inv + hd.z + b.z;
    o.w = acc.w * inv + hd.w + b.w;
    ((float4*)(out + d * HD))[lane] = o;
}

// ---------------- launch ------------------------------------------------------
extern "C" void kernel_launch(void* const* d_in, const int* in_sizes, int n_in,
                              void* d_out, int out_size)
{
    const float* feats  = (const float*)d_in[0];
    const float* W      = (const float*)d_in[1];
    const float* attn_l = (const float*)d_in[2];
    const float* attn_r = (const float*)d_in[3];
    const float* bias   = (const float*)d_in[4];
    const int*   src    = (const int*)d_in[5];
    const int*   dst    = (const int*)d_in[6];
    float* out = (float*)d_out;

    cudaFuncSetAttribute(k_proj, cudaFuncAttributeMaxDynamicSharedMemorySize, K1_SMEM);

    cudaStream_t side;
    cudaEvent_t ev_fork, ev_join;
    cudaStreamCreateWithFlags(&side, cudaStreamNonBlocking);
    cudaEventCreateWithFlags(&ev_fork, cudaEventDisableTiming);
    cudaEventCreateWithFlags(&ev_join, cudaEventDisableTiming);

    cudaEventRecord(ev_fork, 0);
    cudaStreamWaitEvent(side, ev_fork, 0);

    // CSR build chain on side stream (independent of projection)
    k_zero<<<64, 512, 0, side>>>();
    k_hist<<<(N_EDGES / 4 + 255) / 256, 256, 0, side>>>(dst);
    k_scan1<<<SCAN_BLOCKS, 1024, 0, side>>>();
    k_scan2<<<1, 32, 0, side>>>();
    k_scan3<<<SCAN_BLOCKS, 1024, 0, side>>>();
    k_scatter<<<(N_EDGES / 4 + 255) / 256, 256, 0, side>>>(src, dst);
    cudaEventRecord(ev_join, side);

    // projection on the main (captured) stream, concurrent with CSR build
    k_proj<<<296, K1_BLOCK, K1_SMEM>>>(feats, W, attn_l, attn_r);

    cudaStreamWaitEvent(0, ev_join, 0);
    k_agg<<<(N_NODES * 32 + 255) / 256, 256>>>(bias, out);
}

// round 8
// speedup vs baseline: 1.0878x; 1.0878x over previous
#include <cuda_runtime.h>
#include <cuda_fp16.h>
#include <cuda_bf16.h>

#define N_NODES 100000
#define N_EDGES 1600000
#define IN_F    128
#define HEADS   8
#define OUT_F   16
#define HD      128   // HEADS*OUT_F
#define NEG_SLOPE 0.2f

// ---------------- scratch (device globals; no allocation allowed) ------------
__device__ __align__(16) float  g_h  [N_NODES * HD];   // fp32 projected features
__device__ __align__(16) float  g_el [N_NODES * HEADS];
__device__ __align__(16) float  g_er [N_NODES * HEADS];
__device__ __align__(16) int    g_deg   [N_NODES];
__device__ __align__(16) int    g_off   [N_NODES + 4];
__device__ __align__(16) int    g_cursor[N_NODES];
__device__ __align__(16) int    g_csr_src[N_EDGES];
__device__ int g_bsum[32];
__device__ int g_boff[32];

// ---------------- K1: h = feats @ W, el/er  (8 rows per warp, R6 exact) ------
#define K1_BLOCK 256
#define K1_WARPS (K1_BLOCK / 32)                              // 8
#define K1_ROWS  8
#define K1_SMEM  (128*128*4 + K1_WARPS*K1_ROWS*128*4 + 2*128*4)  // 99328 B

__global__ void __launch_bounds__(K1_BLOCK, 2)
k_proj(const float* __restrict__ feats, const float* __restrict__ W,
       const float* __restrict__ attn_l, const float* __restrict__ attn_r)
{
    extern __shared__ float smem[];
    float* Ws   = smem;                              // 128*128
    float* frow = Ws + 128 * 128;                    // 8 warps * 8 rows * 128
    float* al   = frow + K1_WARPS * K1_ROWS * 128;   // 128
    float* ar   = al + 128;                          // 128

    const int tid = threadIdx.x;

    for (int i = tid; i < 128 * 128 / 4; i += K1_BLOCK)
        ((float4*)Ws)[i] = ((const float4*)W)[i];
    if (tid < 128) { al[tid] = attn_l[tid]; ar[tid] = attn_r[tid]; }
    __syncthreads();

    const int warp = tid >> 5, lane = tid & 31;
    const int gw = blockIdx.x * K1_WARPS + warp;
    const int nw = gridDim.x * K1_WARPS;
    float* fr = frow + warp * K1_ROWS * 128;
    const int head  = lane >> 2;
    const int cbase = lane * 4;
    const float4* Ws4 = (const float4*)Ws;

    for (int base = gw * K1_ROWS; base < N_NODES; base += nw * K1_ROWS) {
        #pragma unroll
        for (int r = 0; r < K1_ROWS; r++)
            ((float4*)(fr + r * 128))[lane] = ((const float4*)(feats + (base + r) * IN_F))[lane];
        __syncwarp();

        float4 acc[K1_ROWS];
        #pragma unroll
        for (int r = 0; r < K1_ROWS; r++) acc[r] = make_float4(0.f, 0.f, 0.f, 0.f);

        for (int k4 = 0; k4 < 128; k4 += 4) {
            float f[K1_ROWS][4];
            #pragma unroll
            for (int r = 0; r < K1_ROWS; r++) {
                float4 F = *(const float4*)(fr + r * 128 + k4);
                f[r][0] = F.x; f[r][1] = F.y; f[r][2] = F.z; f[r][3] = F.w;
            }
            #pragma unroll
            for (int kk = 0; kk < 4; kk++) {
                float4 w = Ws4[(k4 + kk) * 32 + lane];
                #pragma unroll
                for (int r = 0; r < K1_ROWS; r++) {
                    acc[r].x += f[r][kk] * w.x;
                    acc[r].y += f[r][kk] * w.y;
                    acc[r].z += f[r][kk] * w.z;
                    acc[r].w += f[r][kk] * w.w;
                }
            }
        }

        #pragma unroll
        for (int r = 0; r < K1_ROWS; r++) {
            float4 a = acc[r];
            int row = base + r;
            float pl = a.x * al[cbase] + a.y * al[cbase+1] + a.z * al[cbase+2] + a.w * al[cbase+3];
            float pr = a.x * ar[cbase] + a.y * ar[cbase+1] + a.z * ar[cbase+2] + a.w * ar[cbase+3];
            pl += __shfl_xor_sync(0xffffffffu, pl, 1);
            pl += __shfl_xor_sync(0xffffffffu, pl, 2);
            pr += __shfl_xor_sync(0xffffffffu, pr, 1);
            pr += __shfl_xor_sync(0xffffffffu, pr, 2);
            if ((lane & 3) == 0) {
                g_el[row * HEADS + head] = pl;
                g_er[row * HEADS + head] = pr;
            }
            ((float4*)(g_h + row * HD))[lane] = a;
        }
        __syncwarp();
    }
}

// ---------------- CSR build (R6 exact) ----------------------------------------
__global__ void __launch_bounds__(512)
k_zero()
{
    for (int i = blockIdx.x * 512 + threadIdx.x; i < N_NODES; i += gridDim.x * 512)
        g_deg[i] = 0;
}

__global__ void __launch_bounds__(256)
k_hist(const int* __restrict__ dst)
{
    int i = blockIdx.x * 256 + threadIdx.x;          // 4 edges per thread
    if (i * 4 >= N_EDGES) return;
    int4 d4 = ((const int4*)dst)[i];
    atomicAdd(&g_deg[d4.x], 1);
    atomicAdd(&g_deg[d4.y], 1);
    atomicAdd(&g_deg[d4.z], 1);
    atomicAdd(&g_deg[d4.w], 1);
}

#define SCAN_BLOCKS ((N_NODES + 4095) / 4096)   // 25

__global__ void __launch_bounds__(1024)
k_scan1()
{
    __shared__ int wsum[32];
    const int tid = threadIdx.x, lane = tid & 31, warp = tid >> 5;
    const int i0 = blockIdx.x * 4096 + tid * 4;

    int4 v = (i0 < N_NODES) ? ((const int4*)g_deg)[i0 >> 2] : make_int4(0, 0, 0, 0);
    int t = v.x + v.y + v.z + v.w;
    int x = t;
    #pragma unroll
    for (int o = 1; o < 32; o <<= 1) {
        int y = __shfl_up_sync(0xffffffffu, x, o);
        if (lane >= o) x += y;
    }
    if (lane == 31) wsum[warp] = x;
    __syncthreads();
    if (warp == 0) {
        int s = wsum[lane];
        #pragma unroll
        for (int o = 1; o < 32; o <<= 1) {
            int y = __shfl_up_sync(0xffffffffu, s, o);
            if (lane >= o) s += y;
        }
        wsum[lane] = s;
    }
    __syncthreads();
    int warpoff = (warp == 0) ? 0 : wsum[warp - 1];
    int excl = warpoff + x - t;
    if (i0 < N_NODES) {
        int4 o;
        o.x = excl;
        o.y = o.x + v.x;
        o.z = o.y + v.y;
        o.w = o.z + v.z;
        ((int4*)g_off)[i0 >> 2] = o;
    }
    if (tid == 0) g_bsum[blockIdx.x] = wsum[31];
}

__global__ void __launch_bounds__(32)
k_scan2()
{
    int lane = threadIdx.x;
    int v = (lane < SCAN_BLOCKS) ? g_bsum[lane] : 0;
    int x = v;
    #pragma unroll
    for (int o = 1; o < 32; o <<= 1) {
        int y = __shfl_up_sync(0xffffffffu, x, o);
        if (lane >= o) x += y;
    }
    if (lane < SCAN_BLOCKS) g_boff[lane] = x - v;
}

__global__ void __launch_bounds__(1024)
k_scan3()
{
    const int i0 = blockIdx.x * 4096 + threadIdx.x * 4;
    if (i0 < N_NODES) {
        int boff = g_boff[blockIdx.x];
        int4 o = ((const int4*)g_off)[i0 >> 2];
        o.x += boff; o.y += boff; o.z += boff; o.w += boff;
        ((int4*)g_off)[i0 >> 2] = o;
        ((int4*)g_cursor)[i0 >> 2] = o;
    }
    if (blockIdx.x == 0 && threadIdx.x == 0) g_off[N_NODES] = N_EDGES;
}

__global__ void __launch_bounds__(256)
k_scatter(const int* __restrict__ src, const int* __restrict__ dst)
{
    int i = blockIdx.x * 256 + threadIdx.x;          // 4 edges per thread
    if (i * 4 >= N_EDGES) return;
    int4 s4 = ((const int4*)src)[i];
    int4 d4 = ((const int4*)dst)[i];
    int p0 = atomicAdd(&g_cursor[d4.x], 1);
    int p1 = atomicAdd(&g_cursor[d4.y], 1);
    int p2 = atomicAdd(&g_cursor[d4.z], 1);
    int p3 = atomicAdd(&g_cursor[d4.w], 1);
    g_csr_src[p0] = s4.x;
    g_csr_src[p1] = s4.y;
    g_csr_src[p2] = s4.z;
    g_csr_src[p3] = s4.w;
}

// ---------------- K3: warp per dst node, batched-exp schedule -----------------
// Per 4-edge batch: lane (q = lane>>3, h = lane&7) computes the exp for
// edge (t+q), head h -> 1 expf + 1 el-LDG per 4 edges. Gather/acc layout is
// the validated R3/R6 one (lane -> cols 4*lane, 1 LDG.128/edge, single acc).
// Invalid edge slots get ex = 0 so the gather+FMA body is predication-free.
__global__ void __launch_bounds__(256)
k_agg(const float* __restrict__ bias, float* __restrict__ out)
{
    const int d = (blockIdx.x * 256 + threadIdx.x) >> 5;
    const int lane = threadIdx.x & 31;
    if (d >= N_NODES) return;
    const int q = lane >> 3;        // edge-in-batch this lane exps for
    const int h = lane & 7;         // head this lane exps for
    const int ghead = lane >> 2;    // head of this lane's gather columns

    const int start = g_off[d], end = g_off[d + 1];
    const float erh = g_er[d * HEADS + h];   // 32B broadcast

    float sum = 0.f;                 // per (q,h) partial head-sum
    float4 acc = {0.f, 0.f, 0.f, 0.f};

    for (int base = start; base < end; base += 32) {
        const int idx = base + lane;
        const int myS = (idx < end) ? __ldg(g_csr_src + idx) : 0;
        const int cnt = min(32, end - base);

        for (int t = 0; t < cnt; t += 4) {
            // ---- batched exp for edges t..t+3 (all 32 lanes useful) ----
            int se = __shfl_sync(0xffffffffu, myS, t + q);
            float a = __ldg(g_el + se * HEADS + h) + erh;
            a = fmaxf(a, 0.f) + NEG_SLOPE * fminf(a, 0.f);
            float ex = (t + q < cnt) ? __expf(a) : 0.f;
            sum += ex;

            // ---- 4 gathers, unconditional (ex==0 kills invalid slots) ----
            #pragma unroll
            for (int u = 0; u < 4; u++) {
                int s = __shfl_sync(0xffffffffu, myS, t + u);
                float exh = __shfl_sync(0xffffffffu, ex, u * 8 + ghead);
                float4 hv = __ldg(((const float4*)(g_h + s * HD)) + lane);
                acc.x += exh * hv.x; acc.y += exh * hv.y;
                acc.z += exh * hv.z; acc.w += exh * hv.w;
            }
        }
    }

    // combine the 4 per-batch-slot partial sums into per-head totals
    sum += __shfl_xor_sync(0xffffffffu, sum, 8);
    sum += __shfl_xor_sync(0xffffffffu, sum, 16);
    // fetch the total for this lane's gather head (src lane l: l&7 == ghead)
    float sumh = __shfl_sync(0xffffffffu, sum, ghead);

    float inv = (end > start) ? 1.f / sumh : 0.f;   // zero in-degree guard
    float4 hd = ((const float4*)(g_h + d * HD))[lane];
    float4 b  = ((const float4*)bias)[lane];
    float4 o;
    o.x = acc.x * inv + hd.x + b.x;
    o.y = acc.y * inv + hd.y + b.y;
    o.z = acc.z * inv + hd.z + b.z;
    o.w = acc.w * inv + hd.w + b.w;
    ((float4*)(out + d * HD))[lane] = o;
}

// ---------------- launch (R6 exact) --------------------------------------------
extern "C" void kernel_launch(void* const* d_in, const int* in_sizes, int n_in,
                              void* d_out, int out_size)
{
    const float* feats  = (const float*)d_in[0];
    const float* W      = (const float*)d_in[1];
    const float* attn_l = (const float*)d_in[2];
    const float* attn_r = (const float*)d_in[3];
    const float* bias   = (const float*)d_in[4];
    const int*   src    = (const int*)d_in[5];
    const int*   dst    = (const int*)d_in[6];
    float* out = (float*)d_out;

    cudaFuncSetAttribute(k_proj, cudaFuncAttributeMaxDynamicSharedMemorySize, K1_SMEM);

    cudaStream_t side;
    cudaEvent_t ev_fork, ev_join;
    cudaStreamCreateWithFlags(&side, cudaStreamNonBlocking);
    cudaEventCreateWithFlags(&ev_fork, cudaEventDisableTiming);
    cudaEventCreateWithFlags(&ev_join, cudaEventDisableTiming);

    cudaEventRecord(ev_fork, 0);
    cudaStreamWaitEvent(side, ev_fork, 0);

    // CSR build chain on side stream (independent of projection)
    k_zero<<<64, 512, 0, side>>>();
    k_hist<<<(N_EDGES / 4 + 255) / 256, 256, 0, side>>>(dst);
    k_scan1<<<SCAN_BLOCKS, 1024, 0, side>>>();
    k_scan2<<<1, 32, 0, side>>>();
    k_scan3<<<SCAN_BLOCKS, 1024, 0, side>>>();
    k_scatter<<<(N_EDGES / 4 + 255) / 256, 256, 0, side>>>(src, dst);
    cudaEventRecord(ev_join, side);

    // projection on the main (captured) stream, concurrent with CSR build
    k_proj<<<296, K1_BLOCK, K1_SMEM>>>(feats, W, attn_l, attn_r);

    cudaStreamWaitEvent(0, ev_join, 0);
    k_agg<<<(N_NODES * 32 + 255) / 256, 256>>>(bias, out);
}